// round 1
// baseline (speedup 1.0000x reference)
#include <cuda_runtime.h>

#define NROWS 2048
#define DFEAT 128
#define BLOCK 256

__global__ __launch_bounds__(BLOCK) void distance_sparse_kernel(
    const float* __restrict__ feats,
    const float* __restrict__ adj,
    float* __restrict__ out)
{
    const int i    = blockIdx.x;
    const int tid  = threadIdx.x;
    const int lane = tid & 31;
    const int warp = tid >> 5;          // 8 warps

    __shared__ float row[NROWS];        // 8 KB: e values for this output row
    __shared__ int   nzidx[NROWS];      // 8 KB: compacted nonzero columns
    __shared__ int   cnt;
    __shared__ float rowsum;

    // feats[i] -> registers: lane l holds elements [4l, 4l+4)
    const float4 fi = reinterpret_cast<const float4*>(feats + (size_t)i * DFEAT)[lane];

    if (tid == 0) { cnt = 0; rowsum = 0.0f; }
    #pragma unroll
    for (int t = tid; t < NROWS; t += BLOCK) row[t] = 0.0f;
    __syncthreads();

    // ---- Phase 1: compact nonzero adjacency columns (float4 scan) ----
    const float4* arow4 = reinterpret_cast<const float4*>(adj + (size_t)i * NROWS);
    #pragma unroll
    for (int t = tid; t < NROWS / 4; t += BLOCK) {
        float4 a = arow4[t];
        int base = t * 4;
        if (a.x != 0.0f) { int p = atomicAdd(&cnt, 1); nzidx[p] = base + 0; }
        if (a.y != 0.0f) { int p = atomicAdd(&cnt, 1); nzidx[p] = base + 1; }
        if (a.z != 0.0f) { int p = atomicAdd(&cnt, 1); nzidx[p] = base + 2; }
        if (a.w != 0.0f) { int p = atomicAdd(&cnt, 1); nzidx[p] = base + 3; }
    }
    __syncthreads();
    const int m = cnt;

    // ---- Phase 2: warp per nonzero column ----
    float wsum = 0.0f;
    for (int k = warp; k < m; k += 8) {
        const int j = nzidx[k];
        const float4 fj = reinterpret_cast<const float4*>(feats + (size_t)j * DFEAT)[lane];
        float s = fabsf(fi.x - fj.x) + fabsf(fi.y - fj.y)
                + fabsf(fi.z - fj.z) + fabsf(fi.w - fj.w);
        s += __shfl_xor_sync(0xffffffffu, s, 16);
        s += __shfl_xor_sync(0xffffffffu, s, 8);
        s += __shfl_xor_sync(0xffffffffu, s, 4);
        s += __shfl_xor_sync(0xffffffffu, s, 2);
        s += __shfl_xor_sync(0xffffffffu, s, 1);
        if (lane == 0) {
            const float e = __expf(-0.01f * s);
            row[j] = e;
            wsum  += e;
        }
    }
    if (lane == 0 && wsum != 0.0f) atomicAdd(&rowsum, wsum);
    __syncthreads();

    // ---- Phase 3: normalize + stream out (float4 stores) ----
    const float inv = 1.0f / fmaxf(rowsum, 1e-12f);
    float4* orow4 = reinterpret_cast<float4*>(out + (size_t)i * NROWS);
    const float4* row4 = reinterpret_cast<const float4*>(row);
    #pragma unroll
    for (int t = tid; t < NROWS / 4; t += BLOCK) {
        float4 v = row4[t];
        v.x *= inv; v.y *= inv; v.z *= inv; v.w *= inv;
        orow4[t] = v;
    }
}

extern "C" void kernel_launch(void* const* d_in, const int* in_sizes, int n_in,
                              void* d_out, int out_size)
{
    const float* feats = (const float*)d_in[0];
    const float* adj   = (const float*)d_in[1];
    float* out         = (float*)d_out;
    distance_sparse_kernel<<<NROWS, BLOCK>>>(feats, adj, out);
}

// round 2
// speedup vs baseline: 1.2526x; 1.2526x over previous
#include <cuda_runtime.h>

#define NROWS 2048
#define DFEAT 128
#define BLOCK 256
#define NWARP (BLOCK / 32)

__global__ __launch_bounds__(BLOCK) void distance_sparse_kernel(
    const float* __restrict__ feats,
    const float* __restrict__ adj,
    float* __restrict__ out)
{
    const int i    = blockIdx.x;
    const int tid  = threadIdx.x;
    const int lane = tid & 31;
    const int warp = tid >> 5;
    const int sub  = lane & 7;    // sublane within 8-lane group
    const int grp  = lane >> 3;   // group 0..3 (one column j per group)

    __shared__ float row[NROWS];     // 8 KB
    __shared__ int   nzidx[NROWS];   // 8 KB
    __shared__ int   cnt;
    __shared__ float rowsum;

    if (tid == 0) { cnt = 0; rowsum = 0.0f; }
    #pragma unroll
    for (int t = tid; t < NROWS; t += BLOCK) row[t] = 0.0f;

    // fi for this lane's role: float4 indices sub + 8t, t=0..3 (L1/L2 cached)
    const float4* fi4p = reinterpret_cast<const float4*>(feats + (size_t)i * DFEAT);
    float4 fi[4];
    #pragma unroll
    for (int t = 0; t < 4; t++) fi[t] = fi4p[sub + 8 * t];
    __syncthreads();

    // ---- Phase 1: ballot-compact nonzero columns (1 atomic per warp per chunk) ----
    const float4* arow4 = reinterpret_cast<const float4*>(adj + (size_t)i * NROWS);
    #pragma unroll
    for (int t = tid; t < NROWS / 4; t += BLOCK) {   // exactly 2 iterations, warp-uniform
        const float4 a = arow4[t];
        const unsigned b0 = __ballot_sync(0xffffffffu, a.x != 0.0f);
        const unsigned b1 = __ballot_sync(0xffffffffu, a.y != 0.0f);
        const unsigned b2 = __ballot_sync(0xffffffffu, a.z != 0.0f);
        const unsigned b3 = __ballot_sync(0xffffffffu, a.w != 0.0f);
        const int c0 = __popc(b0), c1 = __popc(b1), c2 = __popc(b2), c3 = __popc(b3);
        int base = 0;
        if (lane == 0) base = atomicAdd(&cnt, c0 + c1 + c2 + c3);
        base = __shfl_sync(0xffffffffu, base, 0);
        const unsigned lt = (1u << lane) - 1u;
        const int c = t * 4;
        if (a.x != 0.0f) nzidx[base + __popc(b0 & lt)] = c;
        if (a.y != 0.0f) nzidx[base + c0 + __popc(b1 & lt)] = c + 1;
        if (a.z != 0.0f) nzidx[base + c0 + c1 + __popc(b2 & lt)] = c + 2;
        if (a.w != 0.0f) nzidx[base + c0 + c1 + c2 + __popc(b3 & lt)] = c + 3;
    }
    __syncthreads();
    const int m = cnt;

    // ---- Phase 2: 4 columns per warp (8-lane group per column) ----
    float wsum = 0.0f;
    for (int k4 = warp; k4 * 4 < m; k4 += NWARP) {
        const int  idx = k4 * 4 + grp;
        const bool act = idx < m;
        const int  j   = act ? nzidx[idx] : 0;
        const float4* fj4p = reinterpret_cast<const float4*>(feats + (size_t)j * DFEAT);
        float s = 0.0f;
        #pragma unroll
        for (int t = 0; t < 4; t++) {
            const float4 fj = fj4p[sub + 8 * t];
            s += fabsf(fi[t].x - fj.x) + fabsf(fi[t].y - fj.y)
               + fabsf(fi[t].z - fj.z) + fabsf(fi[t].w - fj.w);
        }
        s += __shfl_xor_sync(0xffffffffu, s, 4);
        s += __shfl_xor_sync(0xffffffffu, s, 2);
        s += __shfl_xor_sync(0xffffffffu, s, 1);
        if (act && sub == 0) {
            const float e = __expf(-0.01f * s);
            row[j] = e;
            wsum  += e;
        }
    }
    // reduce the 4 group-leader partials (lanes 0,8,16,24)
    wsum += __shfl_xor_sync(0xffffffffu, wsum, 8);
    wsum += __shfl_xor_sync(0xffffffffu, wsum, 16);
    if (lane == 0 && wsum != 0.0f) atomicAdd(&rowsum, wsum);
    __syncthreads();

    // ---- Phase 3: normalize + stream out ----
    const float inv = 1.0f / fmaxf(rowsum, 1e-12f);
    float4* orow4 = reinterpret_cast<float4*>(out + (size_t)i * NROWS);
    const float4* row4 = reinterpret_cast<const float4*>(row);
    #pragma unroll
    for (int t = tid; t < NROWS / 4; t += BLOCK) {
        float4 v = row4[t];
        v.x *= inv; v.y *= inv; v.z *= inv; v.w *= inv;
        orow4[t] = v;
    }
}

extern "C" void kernel_launch(void* const* d_in, const int* in_sizes, int n_in,
                              void* d_out, int out_size)
{
    const float* feats = (const float*)d_in[0];
    const float* adj   = (const float*)d_in[1];
    float* out         = (float*)d_out;
    distance_sparse_kernel<<<NROWS, BLOCK>>>(feats, adj, out);
}